// round 4
// baseline (speedup 1.0000x reference)
#include <cuda_runtime.h>

// Problem constants (fixed shapes for this problem)
#define N_NODES 20000
#define F_IN    8
#define T_P     12
#define HID     32
#define FEAT    96      // F_IN * T_P floats per node
#define FEAT4   24      // FEAT / 4
#define NTHREADS 256

// ---------------- device scratch (no allocations allowed) ----------------
__device__ float  g_deg [N_NODES];               // degree + 1 (self loop)
__device__ float4 g_agg [N_NODES * FEAT4];       // sum over edges of dinv_s * x_s
__device__ float  g_WLz [F_IN * HID];            // Wz @ Lz_top  (8 x 32)
__device__ float  g_WLh [F_IN * HID];            // Wh @ Lh_top  (8 x 32)
__device__ float  g_blz [HID];                   // bz @ Lz_top + lz
__device__ float  g_blh [HID];                   // bh @ Lh_top + lh
__device__ float  g_probs[T_P];                  // softmax(att)
__device__ unsigned long long g_bar[3];          // monotonic grid barriers

__device__ __forceinline__ float fast_tanh(float x) {
    float y;
    asm("tanh.approx.f32 %0, %1;" : "=f"(y) : "f"(x));
    return y;
}

// Grid-wide barrier. Counters are monotonic across graph replays:
// target = old - old%g + g works because every barrier fully drains
// (counter is an exact multiple of gridDim.x when the kernel retires).
__device__ __forceinline__ void grid_barrier(int which) {
    __syncthreads();
    if (threadIdx.x == 0) {
        __threadfence();                                   // release
        unsigned long long old = atomicAdd(&g_bar[which], 1ULL);
        unsigned long long g = gridDim.x;
        unsigned long long target = old - (old % g) + g;
        unsigned long long v;
        do {
            asm volatile("ld.global.acquire.gpu.u64 %0, [%1];"
                         : "=l"(v) : "l"(&g_bar[which]));
            if (v < target) __nanosleep(64);
        } while (v < target);
        __threadfence();                                   // acquire for block
    }
    __syncthreads();
}

__global__ void __launch_bounds__(NTHREADS)
k_fused(const float* __restrict__ x,
        const int* __restrict__ src, const int* __restrict__ dst, int E,
        const float* __restrict__ Wz, const float* __restrict__ bz,
        const float* __restrict__ Wh, const float* __restrict__ bh,
        const float* __restrict__ Lz, const float* __restrict__ lz,
        const float* __restrict__ Lh, const float* __restrict__ lh,
        const float* __restrict__ att,
        const float* __restrict__ Wout, const float* __restrict__ bout,
        float* __restrict__ out) {
    const int tid     = threadIdx.x;
    const int gtid    = blockIdx.x * NTHREADS + tid;
    const int gstride = gridDim.x * NTHREADS;

    __shared__ float shT[NTHREADS / 32][FEAT];   // time-major node features
    __shared__ float sWout[HID * T_P];
    __shared__ float sBout[T_P];

    // ---------------- Phase 0: init ----------------
    for (int i = gtid; i < N_NODES * FEAT4; i += gstride)
        g_agg[i] = make_float4(0.f, 0.f, 0.f, 0.f);
    for (int i = gtid; i < N_NODES; i += gstride)
        g_deg[i] = 1.0f;                          // +1 self-loop

    if (blockIdx.x == 0) {
        if (tid < F_IN * HID) {
            int f = tid >> 5, h = tid & 31;
            float az = 0.f, ah = 0.f;
            #pragma unroll 8
            for (int k = 0; k < HID; k++) {
                az = fmaf(Wz[f * HID + k], Lz[k * HID + h], az);
                ah = fmaf(Wh[f * HID + k], Lh[k * HID + h], ah);
            }
            g_WLz[tid] = az;
            g_WLh[tid] = ah;
        }
        if (tid < HID) {
            float az = lz[tid], ah = lh[tid];
            for (int k = 0; k < HID; k++) {
                az = fmaf(bz[k], Lz[k * HID + tid], az);
                ah = fmaf(bh[k], Lh[k * HID + tid], ah);
            }
            g_blz[tid] = az;
            g_blh[tid] = ah;
        }
        if (tid == 0) {
            float m = -1e30f;
            for (int t = 0; t < T_P; t++) m = fmaxf(m, att[t]);
            float e[T_P], s = 0.f;
            for (int t = 0; t < T_P; t++) { e[t] = __expf(att[t] - m); s += e[t]; }
            float inv = 1.0f / s;
            for (int t = 0; t < T_P; t++) g_probs[t] = e[t] * inv;
        }
    }
    grid_barrier(0);

    // ---------------- Phase 1: degree count ----------------
    for (int i = gtid; i < E; i += gstride)
        atomicAdd(&g_deg[dst[i]], 1.0f);
    grid_barrier(1);

    // ---------------- Phase 2: scatter  agg[d] += rsqrt(deg[s]) * x[s] ----
    // 8 threads per edge, 3 float4 chunks each (lane-contiguous -> coalesced).
    {
        const float4* x4 = (const float4*)x;
        int total = E * 8;
        for (int i = gtid; i < total; i += gstride) {
            int e   = i >> 3;
            int sub = i & 7;
            int s = __ldg(&src[e]);
            int d = __ldg(&dst[e]);
            float ds = rsqrtf(__ldg(&g_deg[s]));
            const float4* xs = x4 + s * FEAT4;
            float4* ad = g_agg + d * FEAT4;
            #pragma unroll
            for (int k = 0; k < 3; k++) {
                int c = sub + k * 8;
                float4 v = __ldg(&xs[c]);
                asm volatile("red.global.add.v4.f32 [%0], {%1, %2, %3, %4};"
                             :: "l"(&ad[c]), "f"(v.x * ds), "f"(v.y * ds),
                                "f"(v.z * ds), "f"(v.w * ds)
                             : "memory");
            }
        }
    }
    grid_barrier(2);

    // ---------------- Phase 3: node compute ----------------
    // Stage output projection weights in smem (once per block).
    for (int i = tid; i < HID * T_P; i += NTHREADS) sWout[i] = Wout[i];
    if (tid < T_P) sBout[tid] = bout[tid];
    __syncthreads();

    const int w    = tid >> 5;
    const int lane = tid & 31;
    const int warpsTotal = gridDim.x * (NTHREADS / 32);
    const int gwarp      = blockIdx.x * (NTHREADS / 32) + w;

    // Gate weights hoisted out of the node loop (lane == hidden index h).
    float wz[F_IN], wh[F_IN];
    #pragma unroll
    for (int f = 0; f < F_IN; f++) {
        wz[f] = g_WLz[f * HID + lane];
        wh[f] = g_WLh[f * HID + lane];
    }
    const float bz0 = g_blz[lane];
    const float bh0 = g_blh[lane];
    float pr[T_P];
    #pragma unroll
    for (int t = 0; t < T_P; t++) pr[t] = g_probs[t];

    for (int node = gwarp; node < N_NODES; node += warpsTotal) {
        float deg = g_deg[node];
        float dn  = rsqrtf(deg);
        float dn2 = 1.0f / deg;

        // Finalize: full_agg = dn * agg + dn2 * x_self ; store TIME-MAJOR.
        const float* agg = (const float*)g_agg + node * FEAT;
        const float* xn  = x + node * FEAT;
        #pragma unroll
        for (int k = 0; k < 3; k++) {
            int idx = lane + 32 * k;              // idx = f*T_P + t
            float v = dn * agg[idx] + dn2 * __ldg(xn + idx);
            int f = idx / T_P;
            int t = idx - f * T_P;
            shT[w][t * F_IN + f] = v;
        }
        __syncwarp();

        float hacc = 0.f;
        #pragma unroll
        for (int t = 0; t < T_P; t++) {
            float4 xa0 = *(const float4*)&shT[w][t * F_IN];
            float4 xa1 = *(const float4*)&shT[w][t * F_IN + 4];
            float uz = bz0, uh = bh0;
            uz = fmaf(xa0.x, wz[0], uz); uh = fmaf(xa0.x, wh[0], uh);
            uz = fmaf(xa0.y, wz[1], uz); uh = fmaf(xa0.y, wh[1], uh);
            uz = fmaf(xa0.z, wz[2], uz); uh = fmaf(xa0.z, wh[2], uh);
            uz = fmaf(xa0.w, wz[3], uz); uh = fmaf(xa0.w, wh[3], uh);
            uz = fmaf(xa1.x, wz[4], uz); uh = fmaf(xa1.x, wh[4], uh);
            uz = fmaf(xa1.y, wz[5], uz); uh = fmaf(xa1.y, wh[5], uh);
            uz = fmaf(xa1.z, wz[6], uz); uh = fmaf(xa1.z, wh[6], uh);
            uz = fmaf(xa1.w, wz[7], uz); uh = fmaf(xa1.w, wh[7], uh);
            // (1 - sigmoid(uz)) = 0.5*(1 - tanh(uz/2))
            float omz = 0.5f - 0.5f * fast_tanh(0.5f * uz);
            hacc = fmaf(pr[t], omz * fast_tanh(uh), hacc);
        }

        __syncwarp();
        shT[w][lane] = fmaxf(hacc, 0.f);          // relu(H_accum)
        __syncwarp();

        if (lane < T_P) {
            float acc = sBout[lane];
            #pragma unroll
            for (int h = 0; h < HID; h++)
                acc = fmaf(shT[w][h], sWout[h * T_P + lane], acc);
            out[node * T_P + lane] = acc;
        }
        __syncwarp();
    }
}

// ---------------- launch ----------------
extern "C" void kernel_launch(void* const* d_in, const int* in_sizes, int n_in,
                              void* d_out, int out_size) {
    const float* x    = (const float*)d_in[0];   // (N, F_IN, T)
    const int*   ei   = (const int*)  d_in[1];   // (2, E)
    const float* Wz   = (const float*)d_in[2];
    const float* bz   = (const float*)d_in[3];
    // d_in[4], d_in[5]: Wr, br  (dead: H0 == 0)
    const float* Wh   = (const float*)d_in[6];
    const float* bh   = (const float*)d_in[7];
    const float* Lz   = (const float*)d_in[8];
    const float* lz   = (const float*)d_in[9];
    // d_in[10], d_in[11]: Lr, lr (dead)
    const float* Lh   = (const float*)d_in[12];
    const float* lh   = (const float*)d_in[13];
    const float* att  = (const float*)d_in[14];
    const float* Wout = (const float*)d_in[15];
    const float* bout = (const float*)d_in[16];
    float* out = (float*)d_out;

    int E = in_sizes[1] / 2;
    const int* src = ei;
    const int* dst = ei + E;

    // Size the persistent grid to exactly the resident capacity (no deadlock).
    int dev = 0, nsm = 0, perSM = 0;
    cudaGetDevice(&dev);
    cudaDeviceGetAttribute(&nsm, cudaDevAttrMultiProcessorCount, dev);
    cudaOccupancyMaxActiveBlocksPerMultiprocessor(&perSM, k_fused, NTHREADS, 0);
    if (perSM < 1) perSM = 1;
    int grid = nsm * perSM;
    if (grid < 1) grid = 1;

    k_fused<<<grid, NTHREADS>>>(x, src, dst, E,
                                Wz, bz, Wh, bh, Lz, lz, Lh, lh,
                                att, Wout, bout, out);
}

// round 5
// speedup vs baseline: 1.0339x; 1.0339x over previous
#include <cuda_runtime.h>

// Problem constants (fixed shapes for this problem)
#define N_NODES 20000
#define F_IN    8
#define T_P     12
#define HID     32
#define FEAT    96      // F_IN * T_P floats per node
#define FEAT4   24      // FEAT / 4
#define NPW     4       // nodes per warp in k_node (software pipeline)

// ---------------- device scratch (no allocations allowed) ----------------
// One contiguous zero-region: [agg (N*FEAT floats)] [cnt (N floats)]
__device__ float g_zero[N_NODES * FEAT + N_NODES];
__device__ float g_WLz [F_IN * HID];            // Wz @ Lz_top  (8 x 32)
__device__ float g_WLh [F_IN * HID];            // Wh @ Lh_top  (8 x 32)
__device__ float g_blz [HID];                   // bz @ Lz_top + lz
__device__ float g_blh [HID];                   // bh @ Lh_top + lh
__device__ float g_probs[T_P];                  // softmax(att)

#define AGG_OFF 0
#define CNT_OFF (N_NODES * FEAT)

__device__ __forceinline__ float fast_tanh(float x) {
    float y;
    asm("tanh.approx.f32 %0, %1;" : "=f"(y) : "f"(x));
    return y;
}

// ---------------- kernels ----------------

// Tiny 1-block kernel: fold gate weights, biases, softmax(att).
__global__ void k_pre(const float* __restrict__ Wz, const float* __restrict__ bz,
                      const float* __restrict__ Wh, const float* __restrict__ bh,
                      const float* __restrict__ Lz, const float* __restrict__ lz,
                      const float* __restrict__ Lh, const float* __restrict__ lh,
                      const float* __restrict__ att) {
    int tid = threadIdx.x;
    if (tid < F_IN * HID) {
        int f = tid >> 5, h = tid & 31;
        float az = 0.f, ah = 0.f;
        #pragma unroll 8
        for (int k = 0; k < HID; k++) {
            az = fmaf(Wz[f * HID + k], Lz[k * HID + h], az);
            ah = fmaf(Wh[f * HID + k], Lh[k * HID + h], ah);
        }
        g_WLz[tid] = az;
        g_WLh[tid] = ah;
    }
    if (tid < HID) {
        float az = lz[tid], ah = lh[tid];
        for (int k = 0; k < HID; k++) {
            az = fmaf(bz[k], Lz[k * HID + tid], az);
            ah = fmaf(bh[k], Lh[k * HID + tid], ah);
        }
        g_blz[tid] = az;
        g_blh[tid] = ah;
    }
    if (tid == 0) {
        float m = -1e30f;
        for (int t = 0; t < T_P; t++) m = fmaxf(m, att[t]);
        float e[T_P], s = 0.f;
        for (int t = 0; t < T_P; t++) { e[t] = __expf(att[t] - m); s += e[t]; }
        float inv = 1.0f / s;
        for (int t = 0; t < T_P; t++) g_probs[t] = e[t] * inv;
    }
}

// Degree histogram (edges only; self-loop +1 folded in later). 4 edges/thread.
__global__ void k_count(const int4* __restrict__ dst4, int E4) {
    int i = blockIdx.x * blockDim.x + threadIdx.x;
    if (i < E4) {
        int4 d = __ldg(&dst4[i]);
        float* cnt = g_zero + CNT_OFF;
        atomicAdd(&cnt[d.x], 1.0f);
        atomicAdd(&cnt[d.y], 1.0f);
        atomicAdd(&cnt[d.z], 1.0f);
        atomicAdd(&cnt[d.w], 1.0f);
    }
}

// Scatter: agg[dst] += rsqrt(cnt[src]+1) * x[src].   8 threads per edge,
// each thread handles 3 float4 chunks (lane-contiguous -> 128B coalesced).
__global__ void k_scatter(const float4* __restrict__ x4,
                          const int* __restrict__ src,
                          const int* __restrict__ dst, int E) {
    int i = blockIdx.x * blockDim.x + threadIdx.x;
    int e = i >> 3;
    if (e >= E) return;
    int sub = i & 7;
    int s = __ldg(&src[e]);
    int d = __ldg(&dst[e]);
    const float* cnt = g_zero + CNT_OFF;
    float ds = rsqrtf(__ldg(&cnt[s]) + 1.0f);

    const float4* xs = x4 + s * FEAT4;
    float4* ad = (float4*)(g_zero + AGG_OFF) + d * FEAT4;
    #pragma unroll
    for (int k = 0; k < 3; k++) {
        int c = sub + k * 8;
        float4 v = __ldg(&xs[c]);
        asm volatile("red.global.add.v4.f32 [%0], {%1, %2, %3, %4};"
                     :: "l"(&ad[c]), "f"(v.x * ds), "f"(v.y * ds),
                        "f"(v.z * ds), "f"(v.w * ds)
                     : "memory");
    }
}

// One warp handles NPW nodes with a depth-1 load pipeline.
// full_agg[d] = dinv_d * agg[d] + (1/deg_d) * x[d], then gates+attention+out.
__global__ void __launch_bounds__(256)
k_node(const float* __restrict__ x,
       const float* __restrict__ Wout,
       const float* __restrict__ bout,
       float* __restrict__ out) {
    __shared__ float shT[8][FEAT];               // time-major features, per warp
    __shared__ float sWout[HID * T_P];
    __shared__ float sBout[T_P];

    const int tid  = threadIdx.x;
    const int w    = tid >> 5;
    const int lane = tid & 31;

    for (int i = tid; i < HID * T_P; i += 256) sWout[i] = Wout[i];
    if (tid < T_P) sBout[tid] = bout[tid];
    __syncthreads();

    // Gate weights (lane == hidden index h), loaded once per warp.
    float wz[F_IN], wh[F_IN];
    #pragma unroll
    for (int f = 0; f < F_IN; f++) {
        wz[f] = g_WLz[f * HID + lane];
        wh[f] = g_WLh[f * HID + lane];
    }
    const float bz0 = g_blz[lane];
    const float bh0 = g_blh[lane];
    float pr[T_P];
    #pragma unroll
    for (int t = 0; t < T_P; t++) pr[t] = g_probs[t];

    const int gwarp = blockIdx.x * 8 + w;
    const int base  = gwarp * NPW;
    const float4* agg4 = (const float4*)(g_zero + AGG_OFF);
    const float4* x4   = (const float4*)x;
    const float*  cnt  = g_zero + CNT_OFF;

    // Prefetch node 0 of this warp's batch.
    float4 pa0, pa1, pa2, px0, px1, px2;
    float  pcnt;
    {
        int n = base;
        if (n < N_NODES) {
            pa0 = __ldg(&agg4[n * FEAT4 + lane - ((lane >= 24) ? 24 : 0)]); // safe idx
        }
    }
    // NOTE: per-lane layout: each lane loads chunk (lane%24)? Simpler scheme below:
    // lanes 0..23 each own one float4 chunk; lanes 24..31 idle on loads.
    auto load_node = [&](int n, float4& a0, float4& a1, float4& a2,
                         float4& b0, float4& b1, float4& b2, float& c) {
        // 3 chunks of 8 float4 each, lane-contiguous within groups of 8:
        // chunk k: lanes take float4 index (lane&7) + 8k  when (lane>>3)==k? 
        // Simpler: lane loads float4s at indices lane, lane+... but 24 chunks and
        // 32 lanes. Use: lanes 0..23 load chunk=lane. Others load chunk 0 (dummy).
        int c0 = (lane < 24) ? lane : 0;
        a0 = __ldg(&agg4[n * FEAT4 + c0]);
        b0 = __ldg(&x4  [n * FEAT4 + c0]);
        c  = __ldg(&cnt[n]);
        (void)a1; (void)a2; (void)b1; (void)b2;
    };

    // --- straightforward pipelined loop (lane<24 holds one float4 of agg & x) ---
    int n = base;
    float4 A = make_float4(0,0,0,0), X = make_float4(0,0,0,0);
    float  C = 0.f;
    if (n < N_NODES) load_node(n, A, A, A, X, X, X, C);

    for (int j = 0; j < NPW; j++, n++) {
        if (n >= N_NODES) break;
        float4 cA = A, cX = X;
        float  cC = C;
        int nn = n + 1;
        if (j + 1 < NPW && nn < N_NODES) load_node(nn, A, A, A, X, X, X, C);

        float deg = cC + 1.0f;
        float dn  = rsqrtf(deg);
        float dn2 = 1.0f / deg;

        // Finalize + transpose to time-major smem. lane<24 owns float4 chunk 'lane'
        if (lane < 24) {
            float v[4];
            v[0] = dn * cA.x + dn2 * cX.x;
            v[1] = dn * cA.y + dn2 * cX.y;
            v[2] = dn * cA.z + dn2 * cX.z;
            v[3] = dn * cA.w + dn2 * cX.w;
            #pragma unroll
            for (int q = 0; q < 4; q++) {
                int idx = lane * 4 + q;          // idx = f*T_P + t
                int f = idx / T_P;
                int t = idx - f * T_P;
                shT[w][t * F_IN + f] = v[q];
            }
        }
        __syncwarp();

        float hacc = 0.f;
        #pragma unroll
        for (int t = 0; t < T_P; t++) {
            float4 xa0 = *(const float4*)&shT[w][t * F_IN];
            float4 xa1 = *(const float4*)&shT[w][t * F_IN + 4];
            float uz = bz0, uh = bh0;
            uz = fmaf(xa0.x, wz[0], uz); uh = fmaf(xa0.x, wh[0], uh);
            uz = fmaf(xa0.y, wz[1], uz); uh = fmaf(xa0.y, wh[1], uh);
            uz = fmaf(xa0.z, wz[2], uz); uh = fmaf(xa0.z, wh[2], uh);
            uz = fmaf(xa0.w, wz[3], uz); uh = fmaf(xa0.w, wh[3], uh);
            uz = fmaf(xa1.x, wz[4], uz); uh = fmaf(xa1.x, wh[4], uh);
            uz = fmaf(xa1.y, wz[5], uz); uh = fmaf(xa1.y, wh[5], uh);
            uz = fmaf(xa1.z, wz[6], uz); uh = fmaf(xa1.z, wh[6], uh);
            uz = fmaf(xa1.w, wz[7], uz); uh = fmaf(xa1.w, wh[7], uh);
            // (1 - sigmoid(uz)) = 0.5*(1 - tanh(uz/2))
            float omz = 0.5f - 0.5f * fast_tanh(0.5f * uz);
            hacc = fmaf(pr[t], omz * fast_tanh(uh), hacc);
        }

        __syncwarp();
        shT[w][lane] = fmaxf(hacc, 0.f);         // relu(H_accum)
        __syncwarp();

        if (lane < T_P) {
            float acc = sBout[lane];
            #pragma unroll
            for (int h = 0; h < HID; h++)
                acc = fmaf(shT[w][h], sWout[h * T_P + lane], acc);
            out[n * T_P + lane] = acc;
        }
        __syncwarp();
    }
}

// ---------------- launch ----------------
extern "C" void kernel_launch(void* const* d_in, const int* in_sizes, int n_in,
                              void* d_out, int out_size) {
    const float* x    = (const float*)d_in[0];   // (N, F_IN, T)
    const int*   ei   = (const int*)  d_in[1];   // (2, E)
    const float* Wz   = (const float*)d_in[2];
    const float* bz   = (const float*)d_in[3];
    // d_in[4], d_in[5]: Wr, br  (dead: H0 == 0)
    const float* Wh   = (const float*)d_in[6];
    const float* bh   = (const float*)d_in[7];
    const float* Lz   = (const float*)d_in[8];
    const float* lz   = (const float*)d_in[9];
    // d_in[10], d_in[11]: Lr, lr (dead)
    const float* Lh   = (const float*)d_in[12];
    const float* lh   = (const float*)d_in[13];
    const float* att  = (const float*)d_in[14];
    const float* Wout = (const float*)d_in[15];
    const float* bout = (const float*)d_in[16];
    float* out = (float*)d_out;

    int E = in_sizes[1] / 2;
    const int* src = ei;
    const int* dst = ei + E;

    // Zero agg + cnt with a single memset node (graph-capturable).
    void* zptr = nullptr;
    cudaGetSymbolAddress(&zptr, g_zero);
    cudaMemsetAsync(zptr, 0, (size_t)(N_NODES * FEAT + N_NODES) * sizeof(float));

    k_pre<<<1, 256>>>(Wz, bz, Wh, bh, Lz, lz, Lh, lh, att);

    int E4 = E / 4;
    k_count<<<(E4 + 255) / 256, 256>>>((const int4*)dst, E4);

    k_scatter<<<(E * 8 + 255) / 256, 256>>>((const float4*)x, src, dst, E);

    int warps = (N_NODES + NPW - 1) / NPW;
    int blocks = (warps + 7) / 8;
    k_node<<<blocks, 256>>>(x, Wout, bout, out);
}